// round 16
// baseline (speedup 1.0000x reference)
#include <cuda_runtime.h>
#include <cstdint>

// Problem constants (from reference setup_inputs)
#define MAXB   32
#define MAXN   131072
#define TILE   2048          // points per CTA
#define TPB    256           // threads per CTA
#define NPAIR  4             // 4 pair-iterations x 2 points = 8 points/thread
#define MAXTILES (MAXN / TILE)   // 64
#define NWARP  (TPB / 32)
#define NCELL  (NPAIR * NWARP)   // 32 cells (64-point blocks) -> warp scan

// Scratch (allocation-free rule: __device__ globals). ~96 MiB staging buffer:
// tile t of batch b stages its compacted valid rows at rows [t*TILE, t*TILE+cnt).
__device__ float        g_scratch[(size_t)MAXB * MAXN * 6];
__device__ unsigned int g_cnt[MAXB * MAXTILES];

// Validity: bit-matches the JAX reference (verified rel_err=0.0 R3-R15).
// DO NOT change the op order / non-FMA structure.
__device__ __forceinline__ bool is_valid(float x, float y, float z,
                                         float nx, float ny, float nz,
                                         const float* __restrict__ T) {
    float px = __fadd_rn(__fadd_rn(__fadd_rn(__fmul_rn(x, T[0]), __fmul_rn(y, T[4])), __fmul_rn(z, T[8])),  T[3]);
    float py = __fadd_rn(__fadd_rn(__fadd_rn(__fmul_rn(x, T[1]), __fmul_rn(y, T[5])), __fmul_rn(z, T[9])),  T[7]);
    float pz = __fadd_rn(__fadd_rn(__fadd_rn(__fmul_rn(x, T[2]), __fmul_rn(y, T[6])), __fmul_rn(z, T[10])), T[11]);
    float sq = __fadd_rn(__fmul_rn(px, px), __fmul_rn(py, py));
    float ns = __fadd_rn(__fadd_rn(nx, ny), nz);
    return (sq < 1.0f) && (pz < 1.0f) && (ns != 0.0f);
}

// ---------------------------------------------------------------------------
// Kernel 1: stage (UNCHANGED since R12 — measured at the mixed R+W floor,
// 210MB @ ~6.4TB/s = 80% of HBM spec). Direct loads -> classify -> dual-
// ballot rank -> scatter valid rows to scratch + zero whole output slice.
// Point mapping: iter j, warp w, lane l, sub m  ->  p = j*512 + w*64 + 2l + m.
// ---------------------------------------------------------------------------
__global__ void __launch_bounds__(TPB) stage_kernel(const float* __restrict__ pc,
                                                    const float* __restrict__ tf,
                                                    float* __restrict__ out,
                                                    int N, int tiles) {
    __shared__ unsigned int sScan[NCELL];

    const int b    = blockIdx.y;
    const int tile = blockIdx.x;
    const int tid  = threadIdx.x;
    const int lane = tid & 31;
    const int wid  = tid >> 5;
    const float* __restrict__ T = tf + (size_t)b * 16;

    const size_t batch_base = (size_t)b * N;
    const int tile_base = tile * TILE;

    // --- direct loads: 3 consecutive float4 per thread per iter (.cs) ---
    const float4* __restrict__ gsrc =
        (const float4*)(pc + (batch_base + tile_base) * 6);
    float4 d[NPAIR][3];
#pragma unroll
    for (int j = 0; j < NPAIR; j++) {
        const int f4 = j * 768 + 3 * tid;      // 512 points = 768 float4 per iter
        d[j][0] = __ldcs(gsrc + f4 + 0);
        d[j][1] = __ldcs(gsrc + f4 + 1);
        d[j][2] = __ldcs(gsrc + f4 + 2);
    }

    // --- zero this tile's output slice (independent of loads; overlaps) ---
    {
        float4* __restrict__ zdst = (float4*)(out + (batch_base + tile_base) * 6);
        const float4 z4 = make_float4(0.0f, 0.0f, 0.0f, 0.0f);
#pragma unroll
        for (int i = 0; i < TILE * 6 / 4 / TPB; i++)       // 12 float4/thread
            __stcs(zdst + tid + i * TPB, z4);
    }

    // --- classify: 2 points per iter ---
    unsigned int v0bits = 0, v1bits = 0;
#pragma unroll
    for (int j = 0; j < NPAIR; j++) {
        const float4 A = d[j][0], B = d[j][1], C = d[j][2];
        if (is_valid(A.x, A.y, A.z, A.w, B.x, B.y, T)) v0bits |= 1u << j;
        if (is_valid(B.z, B.w, C.x, C.y, C.z, C.w, T)) v1bits |= 1u << j;
    }

    // --- dual ballots per iter -> 32 cell counts ---
    unsigned int b0[NPAIR], b1[NPAIR];
#pragma unroll
    for (int j = 0; j < NPAIR; j++) {
        b0[j] = __ballot_sync(0xFFFFFFFFu, (v0bits >> j) & 1u);
        b1[j] = __ballot_sync(0xFFFFFFFFu, (v1bits >> j) & 1u);
        if (lane == 0) sScan[j * NWARP + wid] = __popc(b0[j]) + __popc(b1[j]);
    }
    __syncthreads();

    // --- warp 0: exclusive scan of 32 cells, publish tile count ---
    if (wid == 0) {
        const unsigned int v = sScan[lane];
        unsigned int x = v;
#pragma unroll
        for (int o = 1; o < 32; o <<= 1) {
            unsigned int y = __shfl_up_sync(0xFFFFFFFFu, x, o);
            if (lane >= o) x += y;
        }
        sScan[lane] = x - v;                               // exclusive
        if (lane == 31) g_cnt[b * tiles + tile] = x;
    }
    __syncthreads();

    // --- scatter valid rows from registers to scratch (default policy: L2) ---
    const unsigned int below = (1u << lane) - 1u;
    float2* __restrict__ gdst = (float2*)(g_scratch + (batch_base + tile_base) * 6);
#pragma unroll
    for (int j = 0; j < NPAIR; j++) {
        const unsigned int excl = sScan[j * NWARP + wid];
        const unsigned int p0   = __popc(b0[j] & below);
        const unsigned int p1   = __popc(b1[j] & below);
        const float4 A = d[j][0], B = d[j][1], C = d[j][2];
        if ((v0bits >> j) & 1u) {
            const unsigned int r = excl + p0 + p1;         // in-block 2l+m order
            gdst[r * 3 + 0] = make_float2(A.x, A.y);
            gdst[r * 3 + 1] = make_float2(A.z, A.w);
            gdst[r * 3 + 2] = make_float2(B.x, B.y);
        }
        if ((v1bits >> j) & 1u) {
            const unsigned int r = excl + p0 + ((v0bits >> j) & 1u) + p1;
            gdst[r * 3 + 0] = make_float2(B.z, B.w);
            gdst[r * 3 + 1] = make_float2(C.x, C.y);
            gdst[r * 3 + 2] = make_float2(C.z, C.w);
        }
    }
}

// ---------------------------------------------------------------------------
// Kernel 2: gather v3 — hybrid of the two measured-best variants:
//  - UNCONDITIONAL first-round prefetch (R15; slice is 3072 float4 so s4[tid]
//    is always in-bounds; removes the cnt->load dependency; ~4KB/CTA)
//  - single-warp count scan + one barrier (R14; keeps regs/occupancy high)
// ---------------------------------------------------------------------------
__global__ void __launch_bounds__(TPB) gather_kernel(float* __restrict__ out,
                                                     int N, int tiles) {
    __shared__ unsigned int sMeta[1];   // [0]=prefix

    const int b    = blockIdx.y;
    const int tile = blockIdx.x;
    const int tid  = threadIdx.x;
    const int lane = tid & 31;
    const int wid  = tid >> 5;
    const size_t batch_base = (size_t)b * N;

    // --- phase 0: unconditional prefetch (issues at cycle ~0) ---
    const float* __restrict__ srcf =
        g_scratch + (batch_base + (size_t)tile * TILE) * 6;
    const float4* __restrict__ s4 = (const float4*)srcf;
    const float4 buf = __ldcs(s4 + tid);
    const unsigned int cnt = __ldg(&g_cnt[b * tiles + tile]);   // overlaps

    // --- phase 1 (concurrent): warp 0 scans the batch's 64 counts ---
    if (wid == 0) {
        const unsigned int c0 = __ldg(&g_cnt[b * tiles + 2 * lane]);
        const unsigned int c1 = __ldg(&g_cnt[b * tiles + 2 * lane + 1]);
        unsigned int s = c0 + c1;
        unsigned int x = s;
#pragma unroll
        for (int o = 1; o < 32; o <<= 1) {
            unsigned int y = __shfl_up_sync(0xFFFFFFFFu, x, o);
            if (lane >= o) x += y;
        }
        const unsigned int excl = x - s;
        const unsigned int pe = __shfl_sync(0xFFFFFFFFu, excl, tile >> 1);
        const unsigned int po = __shfl_sync(0xFFFFFFFFu, excl + c0, tile >> 1);
        if (lane == 0) sMeta[0] = (tile & 1) ? po : pe;
    }
    __syncthreads();
    const unsigned int prefix = sMeta[0];

    const unsigned int nF  = cnt * 6;
    const unsigned int nF4 = nF >> 2;

    // --- phase 2: store prefetched round + guarded remainder + odd tail ---
    float* __restrict__ dstf = out + (batch_base + prefix) * 6;
    if ((prefix & 1u) == 0u) {                             // dst 16B-aligned
        float4* __restrict__ d4 = (float4*)dstf;
        if ((unsigned)tid < nF4) __stcs(d4 + tid, buf);
        for (unsigned int i = tid + TPB; i < nF4; i += TPB)
            __stcs(d4 + i, __ldcs(s4 + i));
    } else {                                               // dst 8B-aligned
        float2* __restrict__ d2 = (float2*)dstf;
        if ((unsigned)tid < nF4) {
            __stcs(d2 + 2 * tid + 0, make_float2(buf.x, buf.y));
            __stcs(d2 + 2 * tid + 1, make_float2(buf.z, buf.w));
        }
        for (unsigned int i = tid + TPB; i < nF4; i += TPB) {
            const float4 v = __ldcs(s4 + i);
            __stcs(d2 + 2 * i + 0, make_float2(v.x, v.y));
            __stcs(d2 + 2 * i + 1, make_float2(v.z, v.w));
        }
    }
    if (tid == 0 && (nF & 3u))                             // cnt odd: 2 floats left
        __stcs((float2*)(dstf + (nF4 << 2)),
               *(const float2*)(srcf + (nF4 << 2)));
}

// ---------------------------------------------------------------------------
extern "C" void kernel_launch(void* const* d_in, const int* in_sizes, int n_in,
                              void* d_out, int out_size) {
    const float* pc = (const float*)d_in[0];   // pointclouds (B, N, 6)
    const float* tf = (const float*)d_in[1];   // task_transform (B, 4, 4)

    const int B = in_sizes[1] / 16;
    const int N = (int)((long long)in_sizes[0] / (6LL * B));
    const int tiles = N / TILE;               // 64

    dim3 grid(tiles, B);
    stage_kernel<<<grid, TPB>>>(pc, tf, (float*)d_out, N, tiles);
    gather_kernel<<<grid, TPB>>>((float*)d_out, N, tiles);
}